// round 13
// baseline (speedup 1.0000x reference)
#include <cuda_runtime.h>
#include <cuda_bf16.h>
#include <cuda_fp16.h>
#include <cstdint>

#define S_LEN   2048
#define BATCH   2
#define DIM     4096
#define NH      32
#define KVHEADS 8
#define HD      128
#define MROWS   (BATCH * S_LEN)     // 4096
#define KVDIM   (KVHEADS * HD)      // 1024
#define KDIM    4096
#define NQKV    (DIM + 2 * KVDIM)   // 6144

// ---------------- scratch (__device__ globals) ------------------------------
__device__ __half g_xh[(size_t)MROWS * KDIM];
__device__ __half g_wqkv[(size_t)NQKV * KDIM];     // wq | wk | wv concatenated
__device__ __half g_woh[(size_t)DIM * KDIM];
__device__ __half g_ah[(size_t)MROWS * DIM];
// post-rope fp16 operands for attention
__device__ __half g_q16[(size_t)MROWS * DIM];
__device__ __half g_k16[(size_t)MROWS * KVDIM];
__device__ __half g_v16[(size_t)MROWS * KVDIM];

// ---------------- helpers ----------------------------------------------
__device__ __forceinline__ uint32_t smem_u32(const void* p) {
    uint32_t a;
    asm("{ .reg .u64 t; cvta.to.shared.u64 t, %1; cvt.u32.u64 %0, t; }"
        : "=r"(a) : "l"(p));
    return a;
}
__device__ __forceinline__ void ldsm4(uint32_t* d, uint32_t addr) {
    asm volatile("ldmatrix.sync.aligned.m8n8.x4.shared.b16 {%0,%1,%2,%3}, [%4];"
                 : "=r"(d[0]), "=r"(d[1]), "=r"(d[2]), "=r"(d[3]) : "r"(addr));
}
__device__ __forceinline__ void ldsm4t(uint32_t* d, uint32_t addr) {
    asm volatile("ldmatrix.sync.aligned.m8n8.x4.trans.shared.b16 {%0,%1,%2,%3}, [%4];"
                 : "=r"(d[0]), "=r"(d[1]), "=r"(d[2]), "=r"(d[3]) : "r"(addr));
}
__device__ __forceinline__ void mma16816h(float* c, const uint32_t* a,
                                          uint32_t b0, uint32_t b1) {
    asm volatile(
        "mma.sync.aligned.m16n8k16.row.col.f32.f16.f16.f32 "
        "{%0,%1,%2,%3}, {%4,%5,%6,%7}, {%8,%9}, {%0,%1,%2,%3};"
        : "+f"(c[0]), "+f"(c[1]), "+f"(c[2]), "+f"(c[3])
        : "r"(a[0]), "r"(a[1]), "r"(a[2]), "r"(a[3]), "r"(b0), "r"(b1));
}
#define CP_ASYNC16(dst, src) \
    asm volatile("cp.async.cg.shared.global [%0], [%1], 16;" \
                 :: "r"(dst), "l"(src) : "memory")
#define CP_COMMIT()  asm volatile("cp.async.commit_group;" ::: "memory")
#define CP_WAIT1()   asm volatile("cp.async.wait_group 1;" ::: "memory")

// ---------------------------------------------------------------------------
// Fused fp32 -> fp16 round: x -> g_xh ; wq|wk|wv -> g_wqkv ; wo -> g_woh
// ---------------------------------------------------------------------------
__global__ void round_all_kernel(const float* __restrict__ x,
                                 const float* __restrict__ wq,
                                 const float* __restrict__ wk,
                                 const float* __restrict__ wv,
                                 const float* __restrict__ wo)
{
    const size_t NB = (size_t)MROWS * KDIM;
    const size_t NK = (size_t)KVDIM * KDIM;
    size_t t = ((size_t)blockIdx.x * blockDim.x + threadIdx.x) * 4;
    const float* src; __half* dst; size_t off;
    if (t < NB)                   { src = x;  dst = g_xh;         off = t; }
    else if (t < 2 * NB)          { src = wq; dst = g_wqkv;       off = t - NB; }
    else if (t < 2 * NB + NK)     { src = wk; dst = g_wqkv + NB;  off = t - 2 * NB; }
    else if (t < 2 * NB + 2 * NK) { src = wv; dst = g_wqkv + NB + NK;
                                    off = t - 2 * NB - NK; }
    else if (t < 3 * NB + 2 * NK) { src = wo; dst = g_woh;
                                    off = t - 2 * NB - 2 * NK; }
    else return;
    float4 f = *(const float4*)(src + off);
    __half2 a = __floats2half2_rn(f.x, f.y);
    __half2 b = __floats2half2_rn(f.z, f.w);
    *(uint2*)(dst + off) = make_uint2(*(uint32_t*)&a, *(uint32_t*)&b);
}

// ---------------------------------------------------------------------------
// GEMM: C[M,N] = Ah[M,K] * Bh[N,K]^T, single fp16 MMA, fp32 accum.
// 128x128 block tile, 128 threads = 4 warps (2x2), 64x64 warp tile, BK=64,
// double-buffered cp.async. MMA:ldsm ratio = 4 (8 ldsm feed 32 MMAs / ks).
// MODE 0: fp32 output (stride DIM). MODE 3: fused QKV epilogue.
// ---------------------------------------------------------------------------
#define BM 128
#define BN 128
#define BK 64
#define PADC 72
#define A_BYTES (BM * PADC * 2)            // 18432
#define B_BYTES (BN * PADC * 2)            // 18432
#define STAGE_BYTES (A_BYTES + B_BYTES)    // 36864
#define GEMM_SMEM   (2 * STAGE_BYTES)      // 73728

template<int MODE>
__global__ void __launch_bounds__(128, 2)
gemm128(const __half* __restrict__ Ah,
        const __half* __restrict__ Bh,
        float* __restrict__ C,
        const float* __restrict__ cosp,
        const float* __restrict__ sinp)
{
    extern __shared__ char smem[];
    const int K = KDIM;
    const uint32_t sbase = smem_u32(smem);
    const int tid = threadIdx.x;
    const int wid = tid >> 5;
    const int lane = tid & 31;
    const int warp_m = wid >> 1;       // 0..1 : 64 rows
    const int warp_n = wid & 1;        // 0..1 : 64 cols
    const int bm = blockIdx.y * BM;
    const int bn = blockIdx.x * BN;
    const int NCH = K / BK;            // 64

    float acc[4][8][4];
#pragma unroll
    for (int i = 0; i < 4; i++)
#pragma unroll
        for (int j = 0; j < 8; j++)
#pragma unroll
            for (int r = 0; r < 4; r++) acc[i][j][r] = 0.f;

    const int a_row = lane & 15;
    const int a_col = (lane >> 4) * 8;
    const int b_row = ((lane >> 4) * 8) + (lane & 7);
    const int b_col = ((lane >> 3) & 1) * 8;

    auto load_stage = [&](int ch, int st) {
        if (ch < NCH) {
            const int kc = ch * BK;
            const uint32_t base = sbase + st * STAGE_BYTES;
#pragma unroll
            for (int i = 0; i < 16; i++) {
                int u = tid + i * 128;          // 0..2047
                int isB = u >> 10;
                int idx = u & 1023;
                int row = idx >> 3, ck = (idx & 7) * 8;
                const __half* src = isB
                    ? Bh + (size_t)(bn + row) * K + kc + ck
                    : Ah + (size_t)(bm + row) * K + kc + ck;
                uint32_t dst = base + isB * A_BYTES
                             + (uint32_t)(row * PADC + ck) * 2;
                CP_ASYNC16(dst, src);
            }
        }
        CP_COMMIT();
    };

    load_stage(0, 0);
    load_stage(1, 1);

    for (int ch = 0; ch < NCH; ch++) {
        const int st = ch & 1;
        CP_WAIT1();
        __syncthreads();
        const uint32_t tb = sbase + st * STAGE_BYTES;
#pragma unroll
        for (int ks = 0; ks < 4; ks++) {
            uint32_t afr[4][4];
#pragma unroll
            for (int mt = 0; mt < 4; mt++) {
                uint32_t addr = tb
                    + (uint32_t)((warp_m * 64 + mt * 16 + a_row) * PADC
                                 + ks * 16 + a_col) * 2;
                ldsm4(afr[mt], addr);
            }
            uint32_t bfr[4][4];
#pragma unroll
            for (int np = 0; np < 4; np++) {
                uint32_t addr = tb + A_BYTES
                    + (uint32_t)((warp_n * 64 + np * 16 + b_row) * PADC
                                 + ks * 16 + b_col) * 2;
                ldsm4(bfr[np], addr);
            }
#pragma unroll
            for (int np = 0; np < 4; np++)
#pragma unroll
                for (int h2 = 0; h2 < 2; h2++) {
                    int nt = np * 2 + h2;
#pragma unroll
                    for (int mt = 0; mt < 4; mt++)
                        mma16816h(acc[mt][nt], afr[mt],
                                  bfr[np][h2 * 2], bfr[np][h2 * 2 + 1]);
                }
        }
        __syncthreads();
        load_stage(ch + 2, st);
    }

    // ---- epilogue -----------------------------------------------------------
#pragma unroll
    for (int mt = 0; mt < 4; mt++)
#pragma unroll
        for (int nt = 0; nt < 8; nt++) {
            int row0 = bm + warp_m * 64 + mt * 16 + (lane >> 2);
            int col  = bn + warp_n * 64 + nt * 8 + (lane & 3) * 2;
            float v0 = acc[mt][nt][0], v1 = acc[mt][nt][1];
            float v2 = acc[mt][nt][2], v3 = acc[mt][nt][3];
            if (MODE == 0) {
                *(float2*)(C + (size_t)row0 * DIM + col) = make_float2(v0, v1);
                *(float2*)(C + (size_t)(row0 + 8) * DIM + col) = make_float2(v2, v3);
            } else {   // MODE 3: fused QKV
                if (col < DIM + KVDIM) {       // Q or K: apply RoPE
                    int i  = (col & 127) >> 1;
                    int s0 = row0 & (S_LEN - 1);
                    int s1 = (row0 + 8) & (S_LEN - 1);
                    float c0 = cosp[s0 * 64 + i], n0 = sinp[s0 * 64 + i];
                    float c1 = cosp[s1 * 64 + i], n1 = sinp[s1 * 64 + i];
                    float t0 = v0 * c0 - v1 * n0; v1 = v0 * n0 + v1 * c0; v0 = t0;
                    float t2 = v2 * c1 - v3 * n1; v3 = v2 * n1 + v3 * c1; v2 = t2;
                }
                __half* dst; int oc; size_t stride;
                if (col < DIM)              { dst = g_q16; oc = col;
                                              stride = DIM; }
                else if (col < DIM + KVDIM) { dst = g_k16; oc = col - DIM;
                                              stride = KVDIM; }
                else                        { dst = g_v16; oc = col - DIM - KVDIM;
                                              stride = KVDIM; }
                *(__half2*)(dst + (size_t)row0 * stride + oc) =
                    __floats2half2_rn(v0, v1);
                *(__half2*)(dst + (size_t)(row0 + 8) * stride + oc) =
                    __floats2half2_rn(v2, v3);
            }
        }
}

// ---------------------------------------------------------------------------
// Tensor-core causal flash attention, single fp16 MMA per tile (unchanged).
// ---------------------------------------------------------------------------
#define APAD   136
#define QSP    (128 * APAD * 2)
#define KVSP   (64 * APAD * 2)
#define ASTAGE (2 * KVSP)
#define ATTN_SMEM (QSP + 2 * ASTAGE)

__global__ void __launch_bounds__(256)
attn_mma()
{
    extern __shared__ char smem[];
    const uint32_t sbase = smem_u32(smem);
    const int tid = threadIdx.x;
    const int warp = tid >> 5;
    const int lane = tid & 31;
    const int qb = blockIdx.x;
    const int h  = blockIdx.y;
    const int b  = blockIdx.z;
    const int kvh = h >> 2;
    const int q0 = qb * 128;
    const int bs = b * S_LEN;
    const int ntiles = 2 * qb + 2;

    const __half* k_b = g_k16 + (size_t)bs * KVDIM + kvh * HD;
    const __half* v_b = g_v16 + (size_t)bs * KVDIM + kvh * HD;

    {
        const __half* q_b = g_q16 + (size_t)(bs + q0) * DIM + h * HD;
#pragma unroll
        for (int i = 0; i < 8; i++) {
            int u = tid + i * 256;
            int row = u >> 4, ck = u & 15;
            const __half* src = q_b + (size_t)row * DIM + ck * 8;
            uint32_t dst = sbase + (uint32_t)(row * APAD + ck * 8) * 2;
            CP_ASYNC16(dst, src);
        }
    }

    auto load_kv = [&](int t, int st) {
        if (t < ntiles) {
            const int k0 = t * 64;
            const uint32_t base = sbase + QSP + st * ASTAGE;
#pragma unroll
            for (int i = 0; i < 8; i++) {
                int u = tid + i * 256;
                int isV = u >> 10;
                int idx = u & 1023;
                int row = idx >> 4, ck = idx & 15;
                const __half* src = (isV ? v_b : k_b)
                                  + (size_t)(k0 + row) * KVDIM + ck * 8;
                uint32_t dst = base + isV * KVSP
                             + (uint32_t)(row * APAD + ck * 8) * 2;
                CP_ASYNC16(dst, src);
            }
        }
        CP_COMMIT();
    };

    load_kv(0, 0);
    load_kv(1, 1);

    const int r0 = lane >> 2;
    const int grow0 = q0 + warp * 16 + r0;
    const int grow1 = grow0 + 8;
    const int wmaxrow = q0 + warp * 16 + 15;
    const float scale = 0.08838834764831845f;

    float m0 = -1e30f, m1 = -1e30f, l0 = 0.f, l1 = 0.f;
    float oacc[16][4];
#pragma unroll
    for (int i = 0; i < 16; i++)
#pragma unroll
        for (int j = 0; j < 4; j++) oacc[i][j] = 0.f;

    const int qa_off = (warp * 16 + (lane & 15)) * APAD + (lane >> 4) * 8;
    const int kb_row = ((lane >> 4) * 8) + (lane & 7);
    const int kb_colh = ((lane >> 3) & 1) * 8;
    const int v_key = (lane & 7) + ((lane >> 3) & 1) * 8;
    const int v_hd  = (lane >> 4) * 8;

    for (int t = 0; t < ntiles; t++) {
        CP_WAIT1();
        __syncthreads();
        const int k0 = t * 64;
        const uint32_t kb = sbase + QSP + (t & 1) * ASTAGE;

        if (k0 <= wmaxrow) {
            float sacc[8][4];
#pragma unroll
            for (int i = 0; i < 8; i++)
#pragma unroll
                for (int j = 0; j < 4; j++) sacc[i][j] = 0.f;

#pragma unroll
            for (int ks = 0; ks < 8; ks++) {
                uint32_t qfr[4];
                ldsm4(qfr, sbase + (uint32_t)(qa_off + ks * 16) * 2);
#pragma unroll
                for (int np = 0; np < 4; np++) {
                    uint32_t kfr[4];
                    uint32_t kaddr = kb
                        + (uint32_t)((np * 16 + kb_row) * APAD + ks * 16 + kb_colh) * 2;
                    ldsm4(kfr, kaddr);
                    mma16816h(sacc[np * 2],     qfr, kfr[0], kfr[1]);
                    mma16816h(sacc[np * 2 + 1], qfr, kfr[2], kfr[3]);
                }
            }

            const bool domask = (t >= 2 * qb);
            float mx0 = -1e30f, mx1 = -1e30f;
#pragma unroll
            for (int nt = 0; nt < 8; nt++) {
                float s0 = sacc[nt][0] * scale;
                float s1 = sacc[nt][1] * scale;
                float s2 = sacc[nt][2] * scale;
                float s3 = sacc[nt][3] * scale;
                if (domask) {
                    int gc = k0 + nt * 8 + 2 * (lane & 3);
                    if (gc > grow0)     s0 = -1e30f;
                    if (gc + 1 > grow0) s1 = -1e30f;
                    if (gc > grow1)     s2 = -1e30f;
                    if (gc + 1 > grow1) s3 = -1e30f;
                }
                sacc[nt][0] = s0; sacc[nt][1] = s1;
                sacc[nt][2] = s2; sacc[nt][3] = s3;
                mx0 = fmaxf(mx0, fmaxf(s0, s1));
                mx1 = fmaxf(mx1, fmaxf(s2, s3));
            }
            mx0 = fmaxf(mx0, __shfl_xor_sync(0xffffffffu, mx0, 1));
            mx0 = fmaxf(mx0, __shfl_xor_sync(0xffffffffu, mx0, 2));
            mx1 = fmaxf(mx1, __shfl_xor_sync(0xffffffffu, mx1, 1));
            mx1 = fmaxf(mx1, __shfl_xor_sync(0xffffffffu, mx1, 2));
            float mn0 = fmaxf(m0, mx0), mn1 = fmaxf(m1, mx1);
            float c0 = __expf(m0 - mn0), c1 = __expf(m1 - mn1);
            m0 = mn0; m1 = mn1;
            l0 *= c0; l1 *= c1;
#pragma unroll
            for (int nt = 0; nt < 16; nt++) {
                oacc[nt][0] *= c0; oacc[nt][1] *= c0;
                oacc[nt][2] *= c1; oacc[nt][3] *= c1;
            }
#pragma unroll
            for (int nt = 0; nt < 8; nt++) {
                float p0 = __expf(sacc[nt][0] - m0);
                float p1 = __expf(sacc[nt][1] - m0);
                float p2 = __expf(sacc[nt][2] - m1);
                float p3 = __expf(sacc[nt][3] - m1);
                sacc[nt][0] = p0; sacc[nt][1] = p1;
                sacc[nt][2] = p2; sacc[nt][3] = p3;
                l0 += p0 + p1; l1 += p2 + p3;
            }

#pragma unroll
            for (int kc = 0; kc < 4; kc++) {
                uint32_t ph[4];
#pragma unroll
                for (int half = 0; half < 2; half++) {
                    const float* pp = sacc[2 * kc + half];
                    __half2 h01 = __floats2half2_rn(pp[0], pp[1]);
                    __half2 h23 = __floats2half2_rn(pp[2], pp[3]);
                    ph[half * 2 + 0] = *(uint32_t*)&h01;
                    ph[half * 2 + 1] = *(uint32_t*)&h23;
                }
#pragma unroll
                for (int np = 0; np < 8; np++) {
                    uint32_t vfr[4];
                    uint32_t vaddr = kb + KVSP
                        + (uint32_t)((kc * 16 + v_key) * APAD + np * 16 + v_hd) * 2;
                    ldsm4t(vfr, vaddr);
                    mma16816h(oacc[2 * np],     ph, vfr[0], vfr[1]);
                    mma16816h(oacc[2 * np + 1], ph, vfr[2], vfr[3]);
                }
            }
        }
        __syncthreads();
        load_kv(t + 2, t & 1);
    }

    l0 += __shfl_xor_sync(0xffffffffu, l0, 1);
    l0 += __shfl_xor_sync(0xffffffffu, l0, 2);
    l1 += __shfl_xor_sync(0xffffffffu, l1, 1);
    l1 += __shfl_xor_sync(0xffffffffu, l1, 2);
    float inv0 = 1.f / l0, inv1 = 1.f / l1;

    size_t gr0 = (size_t)(bs + grow0);
    size_t gr1 = (size_t)(bs + grow1);
#pragma unroll
    for (int nt = 0; nt < 16; nt++) {
        int col = h * HD + nt * 8 + 2 * (lane & 3);
        __half2 h0 = __floats2half2_rn(oacc[nt][0] * inv0, oacc[nt][1] * inv0);
        __half2 h1 = __floats2half2_rn(oacc[nt][2] * inv1, oacc[nt][3] * inv1);
        *(__half2*)(g_ah + gr0 * DIM + col) = h0;
        *(__half2*)(g_ah + gr1 * DIM + col) = h1;
    }
}

// ---------------------------------------------------------------------------
extern "C" void kernel_launch(void* const* d_in, const int* in_sizes, int n_in,
                              void* d_out, int out_size)
{
    (void)in_sizes; (void)n_in; (void)out_size;
    const float* x  = (const float*)d_in[0];
    const float* wq = (const float*)d_in[1];
    const float* wk = (const float*)d_in[2];
    const float* wv = (const float*)d_in[3];
    const float* wo = (const float*)d_in[4];
    const float* fc = (const float*)d_in[5];
    const float* fs = (const float*)d_in[6];
    float* out = (float*)d_out;

    __half *xh, *wqkv, *woh, *ah;
    cudaGetSymbolAddress((void**)&xh,   g_xh);
    cudaGetSymbolAddress((void**)&wqkv, g_wqkv);
    cudaGetSymbolAddress((void**)&woh,  g_woh);
    cudaGetSymbolAddress((void**)&ah,   g_ah);

    cudaFuncSetAttribute(gemm128<0>,
                         cudaFuncAttributeMaxDynamicSharedMemorySize, GEMM_SMEM);
    cudaFuncSetAttribute(gemm128<3>,
                         cudaFuncAttributeMaxDynamicSharedMemorySize, GEMM_SMEM);
    cudaFuncSetAttribute(attn_mma,
                         cudaFuncAttributeMaxDynamicSharedMemorySize, ATTN_SMEM);

    // Fused fp32 -> fp16 rounding (x, wq|wk|wv concat, wo) — one launch
    const size_t total_elems = 3 * (size_t)MROWS * KDIM + 2 * (size_t)KVDIM * KDIM;
    const int rblocks = (int)((total_elems / 4 + 255) / 256);
    round_all_kernel<<<rblocks, 256>>>(x, wq, wk, wv, wo);

    // Fused QKV projection: N = 6144, RoPE + fp16 epilogue by section
    gemm128<3><<<dim3(NQKV / BN, MROWS / BM), 128, GEMM_SMEM>>>(
        xh, wqkv, nullptr, fc, fs);

    // Tensor-core flash attention (fp16) -> writes g_ah
    attn_mma<<<dim3(S_LEN / 128, NH, BATCH), 256, ATTN_SMEM>>>();

    // O projection -> fp32 output
    gemm128<0><<<dim3(DIM / BN, MROWS / BM), 128, GEMM_SMEM>>>(
        ah, woh, out, nullptr, nullptr);
}

// round 14
// speedup vs baseline: 1.0460x; 1.0460x over previous
#include <cuda_runtime.h>
#include <cuda_bf16.h>
#include <cuda_fp16.h>
#include <cstdint>

#define S_LEN   2048
#define BATCH   2
#define DIM     4096
#define NH      32
#define KVHEADS 8
#define HD      128
#define MROWS   (BATCH * S_LEN)     // 4096
#define KVDIM   (KVHEADS * HD)      // 1024
#define KDIM    4096
#define NQKV    (DIM + 2 * KVDIM)   // 6144

// ---------------- scratch (__device__ globals) ------------------------------
__device__ __half g_xh[(size_t)MROWS * KDIM];
__device__ __half g_wqkv[(size_t)NQKV * KDIM];     // wq | wk | wv concatenated
__device__ __half g_woh[(size_t)DIM * KDIM];
__device__ __half g_ah[(size_t)MROWS * DIM];
// post-rope fp16 operands for attention
__device__ __half g_q16[(size_t)MROWS * DIM];
__device__ __half g_k16[(size_t)MROWS * KVDIM];
__device__ __half g_v16[(size_t)MROWS * KVDIM];

// ---------------- helpers ----------------------------------------------
__device__ __forceinline__ uint32_t smem_u32(const void* p) {
    uint32_t a;
    asm("{ .reg .u64 t; cvta.to.shared.u64 t, %1; cvt.u32.u64 %0, t; }"
        : "=r"(a) : "l"(p));
    return a;
}
__device__ __forceinline__ void ldsm4(uint32_t* d, uint32_t addr) {
    asm volatile("ldmatrix.sync.aligned.m8n8.x4.shared.b16 {%0,%1,%2,%3}, [%4];"
                 : "=r"(d[0]), "=r"(d[1]), "=r"(d[2]), "=r"(d[3]) : "r"(addr));
}
__device__ __forceinline__ void ldsm4t(uint32_t* d, uint32_t addr) {
    asm volatile("ldmatrix.sync.aligned.m8n8.x4.trans.shared.b16 {%0,%1,%2,%3}, [%4];"
                 : "=r"(d[0]), "=r"(d[1]), "=r"(d[2]), "=r"(d[3]) : "r"(addr));
}
__device__ __forceinline__ void mma16816h(float* c, const uint32_t* a,
                                          uint32_t b0, uint32_t b1) {
    asm volatile(
        "mma.sync.aligned.m16n8k16.row.col.f32.f16.f16.f32 "
        "{%0,%1,%2,%3}, {%4,%5,%6,%7}, {%8,%9}, {%0,%1,%2,%3};"
        : "+f"(c[0]), "+f"(c[1]), "+f"(c[2]), "+f"(c[3])
        : "r"(a[0]), "r"(a[1]), "r"(a[2]), "r"(a[3]), "r"(b0), "r"(b1));
}
#define CP_ASYNC16(dst, src) \
    asm volatile("cp.async.cg.shared.global [%0], [%1], 16;" \
                 :: "r"(dst), "l"(src) : "memory")
#define CP_COMMIT()  asm volatile("cp.async.commit_group;" ::: "memory")
#define CP_WAIT1()   asm volatile("cp.async.wait_group 1;" ::: "memory")

// ---------------------------------------------------------------------------
// Fused fp32 -> fp16 round: x -> g_xh ; wq|wk|wv -> g_wqkv ; wo -> g_woh
// ---------------------------------------------------------------------------
__global__ void round_all_kernel(const float* __restrict__ x,
                                 const float* __restrict__ wq,
                                 const float* __restrict__ wk,
                                 const float* __restrict__ wv,
                                 const float* __restrict__ wo)
{
    const size_t NB = (size_t)MROWS * KDIM;
    const size_t NK = (size_t)KVDIM * KDIM;
    size_t t = ((size_t)blockIdx.x * blockDim.x + threadIdx.x) * 4;
    const float* src; __half* dst; size_t off;
    if (t < NB)                   { src = x;  dst = g_xh;         off = t; }
    else if (t < 2 * NB)          { src = wq; dst = g_wqkv;       off = t - NB; }
    else if (t < 2 * NB + NK)     { src = wk; dst = g_wqkv + NB;  off = t - 2 * NB; }
    else if (t < 2 * NB + 2 * NK) { src = wv; dst = g_wqkv + NB + NK;
                                    off = t - 2 * NB - NK; }
    else if (t < 3 * NB + 2 * NK) { src = wo; dst = g_woh;
                                    off = t - 2 * NB - 2 * NK; }
    else return;
    float4 f = *(const float4*)(src + off);
    __half2 a = __floats2half2_rn(f.x, f.y);
    __half2 b = __floats2half2_rn(f.z, f.w);
    *(uint2*)(dst + off) = make_uint2(*(uint32_t*)&a, *(uint32_t*)&b);
}

// ---------------------------------------------------------------------------
// GEMM: C[M,N] = Ah[M,K] * Bh[N,K]^T, single fp16 MMA, fp32 accum.
// 128x128 tile, 256 threads = 8 warps (2x4), 64x32 warp tile, BK=64,
// double-buffered cp.async. Persistent tile loop (grid = 2*148 CTAs).
// MODE 0: fp32 output (stride DIM). MODE 3: fused QKV epilogue.
// ---------------------------------------------------------------------------
#define BM 128
#define BN 128
#define BK 64
#define PADC 72
#define A_BYTES (BM * PADC * 2)            // 18432
#define B_BYTES (BN * PADC * 2)            // 18432
#define STAGE_BYTES (A_BYTES + B_BYTES)    // 36864
#define GEMM_SMEM   (2 * STAGE_BYTES)      // 73728
#define GEMM_GRID   296                    // 2 CTAs x 148 SMs

template<int MODE, int NTX>
__global__ void __launch_bounds__(256)
gemm128(const __half* __restrict__ Ah,
        const __half* __restrict__ Bh,
        float* __restrict__ C,
        const float* __restrict__ cosp,
        const float* __restrict__ sinp,
        int ntiles)
{
    extern __shared__ char smem[];
    const int K = KDIM;
    const uint32_t sbase = smem_u32(smem);
    const int tid = threadIdx.x;
    const int wid = tid >> 5;
    const int lane = tid & 31;
    const int warp_m = wid >> 2;       // 0..1 : 64 rows
    const int warp_n = wid & 3;        // 0..3 : 32 cols
    const int NCH = K / BK;            // 64

    const int a_row = lane & 15;
    const int a_col = (lane >> 4) * 8;
    const int b_row = ((lane >> 4) * 8) + (lane & 7);
    const int b_col = ((lane >> 3) & 1) * 8;

    for (int tile = blockIdx.x; tile < ntiles; tile += gridDim.x) {
        const int bm = (tile / NTX) * BM;
        const int bn = (tile % NTX) * BN;

        float acc[4][4][4];
#pragma unroll
        for (int i = 0; i < 4; i++)
#pragma unroll
            for (int j = 0; j < 4; j++)
#pragma unroll
                for (int r = 0; r < 4; r++) acc[i][j][r] = 0.f;

        auto load_stage = [&](int ch, int st) {
            if (ch < NCH) {
                const int kc = ch * BK;
                const uint32_t base = sbase + st * STAGE_BYTES;
#pragma unroll
                for (int i = 0; i < 8; i++) {
                    int u = tid + i * 256;          // 0..2047
                    int isB = u >> 10;
                    int idx = u & 1023;
                    int row = idx >> 3, ck = (idx & 7) * 8;
                    const __half* src = isB
                        ? Bh + (size_t)(bn + row) * K + kc + ck
                        : Ah + (size_t)(bm + row) * K + kc + ck;
                    uint32_t dst = base + isB * A_BYTES
                                 + (uint32_t)(row * PADC + ck) * 2;
                    CP_ASYNC16(dst, src);
                }
            }
            CP_COMMIT();
        };

        load_stage(0, 0);
        load_stage(1, 1);

        for (int ch = 0; ch < NCH; ch++) {
            const int st = ch & 1;
            CP_WAIT1();
            __syncthreads();
            const uint32_t tb = sbase + st * STAGE_BYTES;
#pragma unroll
            for (int ks = 0; ks < 4; ks++) {
                uint32_t afr[4][4];
#pragma unroll
                for (int mt = 0; mt < 4; mt++) {
                    uint32_t addr = tb
                        + (uint32_t)((warp_m * 64 + mt * 16 + a_row) * PADC
                                     + ks * 16 + a_col) * 2;
                    ldsm4(afr[mt], addr);
                }
                uint32_t bfr[2][4];
#pragma unroll
                for (int np = 0; np < 2; np++) {
                    uint32_t addr = tb + A_BYTES
                        + (uint32_t)((warp_n * 32 + np * 16 + b_row) * PADC
                                     + ks * 16 + b_col) * 2;
                    ldsm4(bfr[np], addr);
                }
#pragma unroll
                for (int np = 0; np < 2; np++)
#pragma unroll
                    for (int h2 = 0; h2 < 2; h2++) {
                        int nt = np * 2 + h2;
#pragma unroll
                        for (int mt = 0; mt < 4; mt++)
                            mma16816h(acc[mt][nt], afr[mt],
                                      bfr[np][h2 * 2], bfr[np][h2 * 2 + 1]);
                    }
            }
            __syncthreads();
            load_stage(ch + 2, st);
        }

        // ---- epilogue --------------------------------------------------------
#pragma unroll
        for (int mt = 0; mt < 4; mt++)
#pragma unroll
            for (int nt = 0; nt < 4; nt++) {
                int row0 = bm + warp_m * 64 + mt * 16 + (lane >> 2);
                int col  = bn + warp_n * 32 + nt * 8 + (lane & 3) * 2;
                float v0 = acc[mt][nt][0], v1 = acc[mt][nt][1];
                float v2 = acc[mt][nt][2], v3 = acc[mt][nt][3];
                if (MODE == 0) {
                    *(float2*)(C + (size_t)row0 * DIM + col) =
                        make_float2(v0, v1);
                    *(float2*)(C + (size_t)(row0 + 8) * DIM + col) =
                        make_float2(v2, v3);
                } else {   // MODE 3: fused QKV
                    if (col < DIM + KVDIM) {       // Q or K: apply RoPE
                        int i  = (col & 127) >> 1;
                        int s0 = row0 & (S_LEN - 1);
                        int s1 = (row0 + 8) & (S_LEN - 1);
                        float c0 = cosp[s0 * 64 + i], n0 = sinp[s0 * 64 + i];
                        float c1 = cosp[s1 * 64 + i], n1 = sinp[s1 * 64 + i];
                        float t0 = v0 * c0 - v1 * n0; v1 = v0 * n0 + v1 * c0; v0 = t0;
                        float t2 = v2 * c1 - v3 * n1; v3 = v2 * n1 + v3 * c1; v2 = t2;
                    }
                    __half* dst; int oc; size_t stride;
                    if (col < DIM)              { dst = g_q16; oc = col;
                                                  stride = DIM; }
                    else if (col < DIM + KVDIM) { dst = g_k16; oc = col - DIM;
                                                  stride = KVDIM; }
                    else                        { dst = g_v16;
                                                  oc = col - DIM - KVDIM;
                                                  stride = KVDIM; }
                    *(__half2*)(dst + (size_t)row0 * stride + oc) =
                        __floats2half2_rn(v0, v1);
                    *(__half2*)(dst + (size_t)(row0 + 8) * stride + oc) =
                        __floats2half2_rn(v2, v3);
                }
            }
    }
}

// ---------------------------------------------------------------------------
// Tensor-core causal flash attention, single fp16 MMA per tile.
// qb reversed (largest work first) for better wave packing.
// ---------------------------------------------------------------------------
#define APAD   136
#define QSP    (128 * APAD * 2)
#define KVSP   (64 * APAD * 2)
#define ASTAGE (2 * KVSP)
#define ATTN_SMEM (QSP + 2 * ASTAGE)

__global__ void __launch_bounds__(256)
attn_mma()
{
    extern __shared__ char smem[];
    const uint32_t sbase = smem_u32(smem);
    const int tid = threadIdx.x;
    const int warp = tid >> 5;
    const int lane = tid & 31;
    const int qb = gridDim.x - 1 - blockIdx.x;   // heaviest tiles first
    const int h  = blockIdx.y;
    const int b  = blockIdx.z;
    const int kvh = h >> 2;
    const int q0 = qb * 128;
    const int bs = b * S_LEN;
    const int ntiles = 2 * qb + 2;

    const __half* k_b = g_k16 + (size_t)bs * KVDIM + kvh * HD;
    const __half* v_b = g_v16 + (size_t)bs * KVDIM + kvh * HD;

    {
        const __half* q_b = g_q16 + (size_t)(bs + q0) * DIM + h * HD;
#pragma unroll
        for (int i = 0; i < 8; i++) {
            int u = tid + i * 256;
            int row = u >> 4, ck = u & 15;
            const __half* src = q_b + (size_t)row * DIM + ck * 8;
            uint32_t dst = sbase + (uint32_t)(row * APAD + ck * 8) * 2;
            CP_ASYNC16(dst, src);
        }
    }

    auto load_kv = [&](int t, int st) {
        if (t < ntiles) {
            const int k0 = t * 64;
            const uint32_t base = sbase + QSP + st * ASTAGE;
#pragma unroll
            for (int i = 0; i < 8; i++) {
                int u = tid + i * 256;
                int isV = u >> 10;
                int idx = u & 1023;
                int row = idx >> 4, ck = idx & 15;
                const __half* src = (isV ? v_b : k_b)
                                  + (size_t)(k0 + row) * KVDIM + ck * 8;
                uint32_t dst = base + isV * KVSP
                             + (uint32_t)(row * APAD + ck * 8) * 2;
                CP_ASYNC16(dst, src);
            }
        }
        CP_COMMIT();
    };

    load_kv(0, 0);
    load_kv(1, 1);

    const int r0 = lane >> 2;
    const int grow0 = q0 + warp * 16 + r0;
    const int grow1 = grow0 + 8;
    const int wmaxrow = q0 + warp * 16 + 15;
    const float scale = 0.08838834764831845f;

    float m0 = -1e30f, m1 = -1e30f, l0 = 0.f, l1 = 0.f;
    float oacc[16][4];
#pragma unroll
    for (int i = 0; i < 16; i++)
#pragma unroll
        for (int j = 0; j < 4; j++) oacc[i][j] = 0.f;

    const int qa_off = (warp * 16 + (lane & 15)) * APAD + (lane >> 4) * 8;
    const int kb_row = ((lane >> 4) * 8) + (lane & 7);
    const int kb_colh = ((lane >> 3) & 1) * 8;
    const int v_key = (lane & 7) + ((lane >> 3) & 1) * 8;
    const int v_hd  = (lane >> 4) * 8;

    for (int t = 0; t < ntiles; t++) {
        CP_WAIT1();
        __syncthreads();
        const int k0 = t * 64;
        const uint32_t kb = sbase + QSP + (t & 1) * ASTAGE;

        if (k0 <= wmaxrow) {
            float sacc[8][4];
#pragma unroll
            for (int i = 0; i < 8; i++)
#pragma unroll
                for (int j = 0; j < 4; j++) sacc[i][j] = 0.f;

#pragma unroll
            for (int ks = 0; ks < 8; ks++) {
                uint32_t qfr[4];
                ldsm4(qfr, sbase + (uint32_t)(qa_off + ks * 16) * 2);
#pragma unroll
                for (int np = 0; np < 4; np++) {
                    uint32_t kfr[4];
                    uint32_t kaddr = kb
                        + (uint32_t)((np * 16 + kb_row) * APAD + ks * 16 + kb_colh) * 2;
                    ldsm4(kfr, kaddr);
                    mma16816h(sacc[np * 2],     qfr, kfr[0], kfr[1]);
                    mma16816h(sacc[np * 2 + 1], qfr, kfr[2], kfr[3]);
                }
            }

            const bool domask = (t >= ntiles - 2);
            float mx0 = -1e30f, mx1 = -1e30f;
#pragma unroll
            for (int nt = 0; nt < 8; nt++) {
                float s0 = sacc[nt][0] * scale;
                float s1 = sacc[nt][1] * scale;
                float s2 = sacc[nt][2] * scale;
                float s3 = sacc[nt][3] * scale;
                if (domask) {
                    int gc = k0 + nt * 8 + 2 * (lane & 3);
                    if (gc > grow0)     s0 = -1e30f;
                    if (gc + 1 > grow0) s1 = -1e30f;
                    if (gc > grow1)     s2 = -1e30f;
                    if (gc + 1 > grow1) s3 = -1e30f;
                }
                sacc[nt][0] = s0; sacc[nt][1] = s1;
                sacc[nt][2] = s2; sacc[nt][3] = s3;
                mx0 = fmaxf(mx0, fmaxf(s0, s1));
                mx1 = fmaxf(mx1, fmaxf(s2, s3));
            }
            mx0 = fmaxf(mx0, __shfl_xor_sync(0xffffffffu, mx0, 1));
            mx0 = fmaxf(mx0, __shfl_xor_sync(0xffffffffu, mx0, 2));
            mx1 = fmaxf(mx1, __shfl_xor_sync(0xffffffffu, mx1, 1));
            mx1 = fmaxf(mx1, __shfl_xor_sync(0xffffffffu, mx1, 2));
            float mn0 = fmaxf(m0, mx0), mn1 = fmaxf(m1, mx1);
            float c0 = __expf(m0 - mn0), c1 = __expf(m1 - mn1);
            m0 = mn0; m1 = mn1;
            l0 *= c0; l1 *= c1;
#pragma unroll
            for (int nt = 0; nt < 16; nt++) {
                oacc[nt][0] *= c0; oacc[nt][1] *= c0;
                oacc[nt][2] *= c1; oacc[nt][3] *= c1;
            }
#pragma unroll
            for (int nt = 0; nt < 8; nt++) {
                float p0 = __expf(sacc[nt][0] - m0);
                float p1 = __expf(sacc[nt][1] - m0);
                float p2 = __expf(sacc[nt][2] - m1);
                float p3 = __expf(sacc[nt][3] - m1);
                sacc[nt][0] = p0; sacc[nt][1] = p1;
                sacc[nt][2] = p2; sacc[nt][3] = p3;
                l0 += p0 + p1; l1 += p2 + p3;
            }

#pragma unroll
            for (int kc = 0; kc < 4; kc++) {
                uint32_t ph[4];
#pragma unroll
                for (int half = 0; half < 2; half++) {
                    const float* pp = sacc[2 * kc + half];
                    __half2 h01 = __floats2half2_rn(pp[0], pp[1]);
                    __half2 h23 = __floats2half2_rn(pp[2], pp[3]);
                    ph[half * 2 + 0] = *(uint32_t*)&h01;
                    ph[half * 2 + 1] = *(uint32_t*)&h23;
                }
#pragma unroll
                for (int np = 0; np < 8; np++) {
                    uint32_t vfr[4];
                    uint32_t vaddr = kb + KVSP
                        + (uint32_t)((kc * 16 + v_key) * APAD + np * 16 + v_hd) * 2;
                    ldsm4t(vfr, vaddr);
                    mma16816h(oacc[2 * np],     ph, vfr[0], vfr[1]);
                    mma16816h(oacc[2 * np + 1], ph, vfr[2], vfr[3]);
                }
            }
        }
        __syncthreads();
        load_kv(t + 2, t & 1);
    }

    l0 += __shfl_xor_sync(0xffffffffu, l0, 1);
    l0 += __shfl_xor_sync(0xffffffffu, l0, 2);
    l1 += __shfl_xor_sync(0xffffffffu, l1, 1);
    l1 += __shfl_xor_sync(0xffffffffu, l1, 2);
    float inv0 = 1.f / l0, inv1 = 1.f / l1;

    size_t gr0 = (size_t)(bs + grow0);
    size_t gr1 = (size_t)(bs + grow1);
#pragma unroll
    for (int nt = 0; nt < 16; nt++) {
        int col = h * HD + nt * 8 + 2 * (lane & 3);
        __half2 h0 = __floats2half2_rn(oacc[nt][0] * inv0, oacc[nt][1] * inv0);
        __half2 h1 = __floats2half2_rn(oacc[nt][2] * inv1, oacc[nt][3] * inv1);
        *(__half2*)(g_ah + gr0 * DIM + col) = h0;
        *(__half2*)(g_ah + gr1 * DIM + col) = h1;
    }
}

// ---------------------------------------------------------------------------
extern "C" void kernel_launch(void* const* d_in, const int* in_sizes, int n_in,
                              void* d_out, int out_size)
{
    (void)in_sizes; (void)n_in; (void)out_size;
    const float* x  = (const float*)d_in[0];
    const float* wq = (const float*)d_in[1];
    const float* wk = (const float*)d_in[2];
    const float* wv = (const float*)d_in[3];
    const float* wo = (const float*)d_in[4];
    const float* fc = (const float*)d_in[5];
    const float* fs = (const float*)d_in[6];
    float* out = (float*)d_out;

    __half *xh, *wqkv, *woh, *ah;
    cudaGetSymbolAddress((void**)&xh,   g_xh);
    cudaGetSymbolAddress((void**)&wqkv, g_wqkv);
    cudaGetSymbolAddress((void**)&woh,  g_woh);
    cudaGetSymbolAddress((void**)&ah,   g_ah);

    cudaFuncSetAttribute((gemm128<0, DIM / BN>),
                         cudaFuncAttributeMaxDynamicSharedMemorySize, GEMM_SMEM);
    cudaFuncSetAttribute((gemm128<3, NQKV / BN>),
                         cudaFuncAttributeMaxDynamicSharedMemorySize, GEMM_SMEM);
    cudaFuncSetAttribute(attn_mma,
                         cudaFuncAttributeMaxDynamicSharedMemorySize, ATTN_SMEM);

    // Fused fp32 -> fp16 rounding (x, wq|wk|wv concat, wo) — one launch
    const size_t total_elems = 3 * (size_t)MROWS * KDIM + 2 * (size_t)KVDIM * KDIM;
    const int rblocks = (int)((total_elems / 4 + 255) / 256);
    round_all_kernel<<<rblocks, 256>>>(x, wq, wk, wv, wo);

    // Fused QKV projection (persistent tiles): 48 x 32 = 1536 tiles
    gemm128<3, NQKV / BN><<<GEMM_GRID, 256, GEMM_SMEM>>>(
        xh, wqkv, nullptr, fc, fs, (NQKV / BN) * (MROWS / BM));

    // Tensor-core flash attention (fp16) -> writes g_ah
    attn_mma<<<dim3(S_LEN / 128, NH, BATCH), 256, ATTN_SMEM>>>();

    // O projection (persistent tiles): 32 x 32 = 1024 tiles
    gemm128<0, DIM / BN><<<GEMM_GRID, 256, GEMM_SMEM>>>(
        ah, woh, out, nullptr, nullptr, (DIM / BN) * (MROWS / BM));
}

// round 15
// speedup vs baseline: 1.0606x; 1.0140x over previous
#include <cuda_runtime.h>
#include <cuda_bf16.h>
#include <cuda_fp16.h>
#include <cstdint>

#define S_LEN   2048
#define BATCH   2
#define DIM     4096
#define NH      32
#define KVHEADS 8
#define HD      128
#define MROWS   (BATCH * S_LEN)     // 4096
#define KVDIM   (KVHEADS * HD)      // 1024
#define KDIM    4096
#define NQKV    (DIM + 2 * KVDIM)   // 6144

// ---------------- scratch (__device__ globals) ------------------------------
__device__ __half g_xh[(size_t)MROWS * KDIM];
__device__ __half g_wqkv[(size_t)NQKV * KDIM];     // wq | wk | wv concatenated
__device__ __half g_woh[(size_t)DIM * KDIM];
__device__ __half g_ah[(size_t)MROWS * DIM];
// post-rope fp16 operands for attention
__device__ __half g_q16[(size_t)MROWS * DIM];
__device__ __half g_k16[(size_t)MROWS * KVDIM];
__device__ __half g_v16[(size_t)MROWS * KVDIM];

// ---------------- helpers ----------------------------------------------
__device__ __forceinline__ uint32_t smem_u32(const void* p) {
    uint32_t a;
    asm("{ .reg .u64 t; cvta.to.shared.u64 t, %1; cvt.u32.u64 %0, t; }"
        : "=r"(a) : "l"(p));
    return a;
}
__device__ __forceinline__ void ldsm4(uint32_t* d, uint32_t addr) {
    asm volatile("ldmatrix.sync.aligned.m8n8.x4.shared.b16 {%0,%1,%2,%3}, [%4];"
                 : "=r"(d[0]), "=r"(d[1]), "=r"(d[2]), "=r"(d[3]) : "r"(addr));
}
__device__ __forceinline__ void ldsm4t(uint32_t* d, uint32_t addr) {
    asm volatile("ldmatrix.sync.aligned.m8n8.x4.trans.shared.b16 {%0,%1,%2,%3}, [%4];"
                 : "=r"(d[0]), "=r"(d[1]), "=r"(d[2]), "=r"(d[3]) : "r"(addr));
}
__device__ __forceinline__ void mma16816h(float* c, const uint32_t* a,
                                          uint32_t b0, uint32_t b1) {
    asm volatile(
        "mma.sync.aligned.m16n8k16.row.col.f32.f16.f16.f32 "
        "{%0,%1,%2,%3}, {%4,%5,%6,%7}, {%8,%9}, {%0,%1,%2,%3};"
        : "+f"(c[0]), "+f"(c[1]), "+f"(c[2]), "+f"(c[3])
        : "r"(a[0]), "r"(a[1]), "r"(a[2]), "r"(a[3]), "r"(b0), "r"(b1));
}
#define CP_ASYNC16(dst, src) \
    asm volatile("cp.async.cg.shared.global [%0], [%1], 16;" \
                 :: "r"(dst), "l"(src) : "memory")
#define CP_COMMIT()  asm volatile("cp.async.commit_group;" ::: "memory")
#define CP_WAIT1()   asm volatile("cp.async.wait_group 1;" ::: "memory")

// ---------------------------------------------------------------------------
// Fused fp32 -> fp16 round: x -> g_xh ; wq|wk|wv -> g_wqkv ; wo -> g_woh
// ---------------------------------------------------------------------------
__global__ void round_all_kernel(const float* __restrict__ x,
                                 const float* __restrict__ wq,
                                 const float* __restrict__ wk,
                                 const float* __restrict__ wv,
                                 const float* __restrict__ wo)
{
    const size_t NB = (size_t)MROWS * KDIM;
    const size_t NK = (size_t)KVDIM * KDIM;
    size_t t = ((size_t)blockIdx.x * blockDim.x + threadIdx.x) * 4;
    const float* src; __half* dst; size_t off;
    if (t < NB)                   { src = x;  dst = g_xh;         off = t; }
    else if (t < 2 * NB)          { src = wq; dst = g_wqkv;       off = t - NB; }
    else if (t < 2 * NB + NK)     { src = wk; dst = g_wqkv + NB;  off = t - 2 * NB; }
    else if (t < 2 * NB + 2 * NK) { src = wv; dst = g_wqkv + NB + NK;
                                    off = t - 2 * NB - NK; }
    else if (t < 3 * NB + 2 * NK) { src = wo; dst = g_woh;
                                    off = t - 2 * NB - 2 * NK; }
    else return;
    float4 f = *(const float4*)(src + off);
    __half2 a = __floats2half2_rn(f.x, f.y);
    __half2 b = __floats2half2_rn(f.z, f.w);
    *(uint2*)(dst + off) = make_uint2(*(uint32_t*)&a, *(uint32_t*)&b);
}

// ---------------------------------------------------------------------------
// GEMM (round-12 engine): C[M,N] = Ah[M,K] * Bh[N,K]^T, single fp16 MMA.
// 128x128 tile, 256 threads = 8 warps (2x4), 64x32 warp tile, BK=64,
// double-buffered cp.async, one CTA per tile.
// MODE 0: fp32 output (stride DIM). MODE 3: fused QKV epilogue.
// ---------------------------------------------------------------------------
#define BM 128
#define BN 128
#define BK 64
#define PADC 72
#define A_BYTES (BM * PADC * 2)            // 18432
#define B_BYTES (BN * PADC * 2)            // 18432
#define STAGE_BYTES (A_BYTES + B_BYTES)    // 36864
#define GEMM_SMEM   (2 * STAGE_BYTES)      // 73728

template<int MODE>
__global__ void __launch_bounds__(256)
gemm128(const __half* __restrict__ Ah,
        const __half* __restrict__ Bh,
        float* __restrict__ C,
        const float* __restrict__ cosp,
        const float* __restrict__ sinp)
{
    extern __shared__ char smem[];
    const int K = KDIM;
    const uint32_t sbase = smem_u32(smem);
    const int tid = threadIdx.x;
    const int wid = tid >> 5;
    const int lane = tid & 31;
    const int warp_m = wid >> 2;       // 0..1 : 64 rows
    const int warp_n = wid & 3;        // 0..3 : 32 cols
    const int bm = blockIdx.y * BM;
    const int bn = blockIdx.x * BN;
    const int NCH = K / BK;            // 64

    float acc[4][4][4];
#pragma unroll
    for (int i = 0; i < 4; i++)
#pragma unroll
        for (int j = 0; j < 4; j++)
#pragma unroll
            for (int r = 0; r < 4; r++) acc[i][j][r] = 0.f;

    const int a_row = lane & 15;
    const int a_col = (lane >> 4) * 8;
    const int b_row = ((lane >> 4) * 8) + (lane & 7);
    const int b_col = ((lane >> 3) & 1) * 8;

    auto load_stage = [&](int ch, int st) {
        if (ch < NCH) {
            const int kc = ch * BK;
            const uint32_t base = sbase + st * STAGE_BYTES;
#pragma unroll
            for (int i = 0; i < 8; i++) {
                int u = tid + i * 256;          // 0..2047
                int isB = u >> 10;
                int idx = u & 1023;
                int row = idx >> 3, ck = (idx & 7) * 8;
                const __half* src = isB
                    ? Bh + (size_t)(bn + row) * K + kc + ck
                    : Ah + (size_t)(bm + row) * K + kc + ck;
                uint32_t dst = base + isB * A_BYTES
                             + (uint32_t)(row * PADC + ck) * 2;
                CP_ASYNC16(dst, src);
            }
        }
        CP_COMMIT();
    };

    load_stage(0, 0);
    load_stage(1, 1);

    for (int ch = 0; ch < NCH; ch++) {
        const int st = ch & 1;
        CP_WAIT1();
        __syncthreads();
        const uint32_t tb = sbase + st * STAGE_BYTES;
#pragma unroll
        for (int ks = 0; ks < 4; ks++) {
            uint32_t afr[4][4];
#pragma unroll
            for (int mt = 0; mt < 4; mt++) {
                uint32_t addr = tb
                    + (uint32_t)((warp_m * 64 + mt * 16 + a_row) * PADC
                                 + ks * 16 + a_col) * 2;
                ldsm4(afr[mt], addr);
            }
            uint32_t bfr[2][4];
#pragma unroll
            for (int np = 0; np < 2; np++) {
                uint32_t addr = tb + A_BYTES
                    + (uint32_t)((warp_n * 32 + np * 16 + b_row) * PADC
                                 + ks * 16 + b_col) * 2;
                ldsm4(bfr[np], addr);
            }
#pragma unroll
            for (int np = 0; np < 2; np++)
#pragma unroll
                for (int h2 = 0; h2 < 2; h2++) {
                    int nt = np * 2 + h2;
#pragma unroll
                    for (int mt = 0; mt < 4; mt++)
                        mma16816h(acc[mt][nt], afr[mt],
                                  bfr[np][h2 * 2], bfr[np][h2 * 2 + 1]);
                }
        }
        __syncthreads();
        load_stage(ch + 2, st);
    }

    // ---- epilogue -----------------------------------------------------------
#pragma unroll
    for (int mt = 0; mt < 4; mt++)
#pragma unroll
        for (int nt = 0; nt < 4; nt++) {
            int row0 = bm + warp_m * 64 + mt * 16 + (lane >> 2);
            int col  = bn + warp_n * 32 + nt * 8 + (lane & 3) * 2;
            float v0 = acc[mt][nt][0], v1 = acc[mt][nt][1];
            float v2 = acc[mt][nt][2], v3 = acc[mt][nt][3];
            if (MODE == 0) {
                *(float2*)(C + (size_t)row0 * DIM + col) = make_float2(v0, v1);
                *(float2*)(C + (size_t)(row0 + 8) * DIM + col) = make_float2(v2, v3);
            } else {   // MODE 3: fused QKV
                if (col < DIM + KVDIM) {       // Q or K: apply RoPE
                    int i  = (col & 127) >> 1;
                    int s0 = row0 & (S_LEN - 1);
                    int s1 = (row0 + 8) & (S_LEN - 1);
                    float c0 = cosp[s0 * 64 + i], n0 = sinp[s0 * 64 + i];
                    float c1 = cosp[s1 * 64 + i], n1 = sinp[s1 * 64 + i];
                    float t0 = v0 * c0 - v1 * n0; v1 = v0 * n0 + v1 * c0; v0 = t0;
                    float t2 = v2 * c1 - v3 * n1; v3 = v2 * n1 + v3 * c1; v2 = t2;
                }
                __half* dst; int oc; size_t stride;
                if (col < DIM)              { dst = g_q16; oc = col;
                                              stride = DIM; }
                else if (col < DIM + KVDIM) { dst = g_k16; oc = col - DIM;
                                              stride = KVDIM; }
                else                        { dst = g_v16; oc = col - DIM - KVDIM;
                                              stride = KVDIM; }
                *(__half2*)(dst + (size_t)row0 * stride + oc) =
                    __floats2half2_rn(v0, v1);
                *(__half2*)(dst + (size_t)(row0 + 8) * stride + oc) =
                    __floats2half2_rn(v2, v3);
            }
        }
}

// ---------------------------------------------------------------------------
// Tensor-core causal flash attention, single fp16 MMA per tile.
// qb reversed (largest work first) for better wave packing.
// ---------------------------------------------------------------------------
#define APAD   136
#define QSP    (128 * APAD * 2)
#define KVSP   (64 * APAD * 2)
#define ASTAGE (2 * KVSP)
#define ATTN_SMEM (QSP + 2 * ASTAGE)

__global__ void __launch_bounds__(256)
attn_mma()
{
    extern __shared__ char smem[];
    const uint32_t sbase = smem_u32(smem);
    const int tid = threadIdx.x;
    const int warp = tid >> 5;
    const int lane = tid & 31;
    const int qb = gridDim.x - 1 - blockIdx.x;   // heaviest tiles first
    const int h  = blockIdx.y;
    const int b  = blockIdx.z;
    const int kvh = h >> 2;
    const int q0 = qb * 128;
    const int bs = b * S_LEN;
    const int ntiles = 2 * qb + 2;

    const __half* k_b = g_k16 + (size_t)bs * KVDIM + kvh * HD;
    const __half* v_b = g_v16 + (size_t)bs * KVDIM + kvh * HD;

    {
        const __half* q_b = g_q16 + (size_t)(bs + q0) * DIM + h * HD;
#pragma unroll
        for (int i = 0; i < 8; i++) {
            int u = tid + i * 256;
            int row = u >> 4, ck = u & 15;
            const __half* src = q_b + (size_t)row * DIM + ck * 8;
            uint32_t dst = sbase + (uint32_t)(row * APAD + ck * 8) * 2;
            CP_ASYNC16(dst, src);
        }
    }

    auto load_kv = [&](int t, int st) {
        if (t < ntiles) {
            const int k0 = t * 64;
            const uint32_t base = sbase + QSP + st * ASTAGE;
#pragma unroll
            for (int i = 0; i < 8; i++) {
                int u = tid + i * 256;
                int isV = u >> 10;
                int idx = u & 1023;
                int row = idx >> 4, ck = idx & 15;
                const __half* src = (isV ? v_b : k_b)
                                  + (size_t)(k0 + row) * KVDIM + ck * 8;
                uint32_t dst = base + isV * KVSP
                             + (uint32_t)(row * APAD + ck * 8) * 2;
                CP_ASYNC16(dst, src);
            }
        }
        CP_COMMIT();
    };

    load_kv(0, 0);
    load_kv(1, 1);

    const int r0 = lane >> 2;
    const int grow0 = q0 + warp * 16 + r0;
    const int grow1 = grow0 + 8;
    const int wmaxrow = q0 + warp * 16 + 15;
    const float scale = 0.08838834764831845f;

    float m0 = -1e30f, m1 = -1e30f, l0 = 0.f, l1 = 0.f;
    float oacc[16][4];
#pragma unroll
    for (int i = 0; i < 16; i++)
#pragma unroll
        for (int j = 0; j < 4; j++) oacc[i][j] = 0.f;

    const int qa_off = (warp * 16 + (lane & 15)) * APAD + (lane >> 4) * 8;
    const int kb_row = ((lane >> 4) * 8) + (lane & 7);
    const int kb_colh = ((lane >> 3) & 1) * 8;
    const int v_key = (lane & 7) + ((lane >> 3) & 1) * 8;
    const int v_hd  = (lane >> 4) * 8;

    for (int t = 0; t < ntiles; t++) {
        CP_WAIT1();
        __syncthreads();
        const int k0 = t * 64;
        const uint32_t kb = sbase + QSP + (t & 1) * ASTAGE;

        if (k0 <= wmaxrow) {
            float sacc[8][4];
#pragma unroll
            for (int i = 0; i < 8; i++)
#pragma unroll
                for (int j = 0; j < 4; j++) sacc[i][j] = 0.f;

#pragma unroll
            for (int ks = 0; ks < 8; ks++) {
                uint32_t qfr[4];
                ldsm4(qfr, sbase + (uint32_t)(qa_off + ks * 16) * 2);
#pragma unroll
                for (int np = 0; np < 4; np++) {
                    uint32_t kfr[4];
                    uint32_t kaddr = kb
                        + (uint32_t)((np * 16 + kb_row) * APAD + ks * 16 + kb_colh) * 2;
                    ldsm4(kfr, kaddr);
                    mma16816h(sacc[np * 2],     qfr, kfr[0], kfr[1]);
                    mma16816h(sacc[np * 2 + 1], qfr, kfr[2], kfr[3]);
                }
            }

            const bool domask = (t >= ntiles - 2);
            float mx0 = -1e30f, mx1 = -1e30f;
#pragma unroll
            for (int nt = 0; nt < 8; nt++) {
                float s0 = sacc[nt][0] * scale;
                float s1 = sacc[nt][1] * scale;
                float s2 = sacc[nt][2] * scale;
                float s3 = sacc[nt][3] * scale;
                if (domask) {
                    int gc = k0 + nt * 8 + 2 * (lane & 3);
                    if (gc > grow0)     s0 = -1e30f;
                    if (gc + 1 > grow0) s1 = -1e30f;
                    if (gc > grow1)     s2 = -1e30f;
                    if (gc + 1 > grow1) s3 = -1e30f;
                }
                sacc[nt][0] = s0; sacc[nt][1] = s1;
                sacc[nt][2] = s2; sacc[nt][3] = s3;
                mx0 = fmaxf(mx0, fmaxf(s0, s1));
                mx1 = fmaxf(mx1, fmaxf(s2, s3));
            }
            mx0 = fmaxf(mx0, __shfl_xor_sync(0xffffffffu, mx0, 1));
            mx0 = fmaxf(mx0, __shfl_xor_sync(0xffffffffu, mx0, 2));
            mx1 = fmaxf(mx1, __shfl_xor_sync(0xffffffffu, mx1, 1));
            mx1 = fmaxf(mx1, __shfl_xor_sync(0xffffffffu, mx1, 2));
            float mn0 = fmaxf(m0, mx0), mn1 = fmaxf(m1, mx1);
            float c0 = __expf(m0 - mn0), c1 = __expf(m1 - mn1);
            m0 = mn0; m1 = mn1;
            l0 *= c0; l1 *= c1;
#pragma unroll
            for (int nt = 0; nt < 16; nt++) {
                oacc[nt][0] *= c0; oacc[nt][1] *= c0;
                oacc[nt][2] *= c1; oacc[nt][3] *= c1;
            }
#pragma unroll
            for (int nt = 0; nt < 8; nt++) {
                float p0 = __expf(sacc[nt][0] - m0);
                float p1 = __expf(sacc[nt][1] - m0);
                float p2 = __expf(sacc[nt][2] - m1);
                float p3 = __expf(sacc[nt][3] - m1);
                sacc[nt][0] = p0; sacc[nt][1] = p1;
                sacc[nt][2] = p2; sacc[nt][3] = p3;
                l0 += p0 + p1; l1 += p2 + p3;
            }

#pragma unroll
            for (int kc = 0; kc < 4; kc++) {
                uint32_t ph[4];
#pragma unroll
                for (int half = 0; half < 2; half++) {
                    const float* pp = sacc[2 * kc + half];
                    __half2 h01 = __floats2half2_rn(pp[0], pp[1]);
                    __half2 h23 = __floats2half2_rn(pp[2], pp[3]);
                    ph[half * 2 + 0] = *(uint32_t*)&h01;
                    ph[half * 2 + 1] = *(uint32_t*)&h23;
                }
#pragma unroll
                for (int np = 0; np < 8; np++) {
                    uint32_t vfr[4];
                    uint32_t vaddr = kb + KVSP
                        + (uint32_t)((kc * 16 + v_key) * APAD + np * 16 + v_hd) * 2;
                    ldsm4t(vfr, vaddr);
                    mma16816h(oacc[2 * np],     ph, vfr[0], vfr[1]);
                    mma16816h(oacc[2 * np + 1], ph, vfr[2], vfr[3]);
                }
            }
        }
        __syncthreads();
        load_kv(t + 2, t & 1);
    }

    l0 += __shfl_xor_sync(0xffffffffu, l0, 1);
    l0 += __shfl_xor_sync(0xffffffffu, l0, 2);
    l1 += __shfl_xor_sync(0xffffffffu, l1, 1);
    l1 += __shfl_xor_sync(0xffffffffu, l1, 2);
    float inv0 = 1.f / l0, inv1 = 1.f / l1;

    size_t gr0 = (size_t)(bs + grow0);
    size_t gr1 = (size_t)(bs + grow1);
#pragma unroll
    for (int nt = 0; nt < 16; nt++) {
        int col = h * HD + nt * 8 + 2 * (lane & 3);
        __half2 h0 = __floats2half2_rn(oacc[nt][0] * inv0, oacc[nt][1] * inv0);
        __half2 h1 = __floats2half2_rn(oacc[nt][2] * inv1, oacc[nt][3] * inv1);
        *(__half2*)(g_ah + gr0 * DIM + col) = h0;
        *(__half2*)(g_ah + gr1 * DIM + col) = h1;
    }
}

// ---------------------------------------------------------------------------
extern "C" void kernel_launch(void* const* d_in, const int* in_sizes, int n_in,
                              void* d_out, int out_size)
{
    (void)in_sizes; (void)n_in; (void)out_size;
    const float* x  = (const float*)d_in[0];
    const float* wq = (const float*)d_in[1];
    const float* wk = (const float*)d_in[2];
    const float* wv = (const float*)d_in[3];
    const float* wo = (const float*)d_in[4];
    const float* fc = (const float*)d_in[5];
    const float* fs = (const float*)d_in[6];
    float* out = (float*)d_out;

    __half *xh, *wqkv, *woh, *ah;
    cudaGetSymbolAddress((void**)&xh,   g_xh);
    cudaGetSymbolAddress((void**)&wqkv, g_wqkv);
    cudaGetSymbolAddress((void**)&woh,  g_woh);
    cudaGetSymbolAddress((void**)&ah,   g_ah);

    cudaFuncSetAttribute(gemm128<0>,
                         cudaFuncAttributeMaxDynamicSharedMemorySize, GEMM_SMEM);
    cudaFuncSetAttribute(gemm128<3>,
                         cudaFuncAttributeMaxDynamicSharedMemorySize, GEMM_SMEM);
    cudaFuncSetAttribute(attn_mma,
                         cudaFuncAttributeMaxDynamicSharedMemorySize, ATTN_SMEM);

    // Fused fp32 -> fp16 rounding (x, wq|wk|wv concat, wo) — one launch
    const size_t total_elems = 3 * (size_t)MROWS * KDIM + 2 * (size_t)KVDIM * KDIM;
    const int rblocks = (int)((total_elems / 4 + 255) / 256);
    round_all_kernel<<<rblocks, 256>>>(x, wq, wk, wv, wo);

    // Fused QKV projection: N = 6144, RoPE + fp16 epilogue by section
    gemm128<3><<<dim3(NQKV / BN, MROWS / BM), 256, GEMM_SMEM>>>(
        xh, wqkv, nullptr, fc, fs);

    // Tensor-core flash attention (fp16, reversed qb) -> writes g_ah
    attn_mma<<<dim3(S_LEN / 128, NH, BATCH), 256, ATTN_SMEM>>>();

    // O projection -> fp32 output
    gemm128<0><<<dim3(DIM / BN, MROWS / BM), 256, GEMM_SMEM>>>(
        ah, woh, out, nullptr, nullptr);
}